// round 6
// baseline (speedup 1.0000x reference)
#include <cuda_runtime.h>
#include <cuda_fp16.h>
#include <cstdint>

#define NE    16
#define NTOK  4096
#define INF   1024
#define OUTF  2048
#define BM    128
#define BN    128
#define BK    32
#define NKI   (INF / BK)          // 32 k-chunks
#define MAXMT (NTOK / BM + NE)    // 48 worst-case m-tiles
#define LDAH  40                  // smem row stride in halves (32 + 8 pad)

// ---- device scratch ----
__device__ int    g_off[NE + 1];
__device__ int    g_sorted[NTOK];
__device__ int    g_tile[NE + 1];
__device__ __half g_xh[NTOK * INF];   // x rounded to fp16 (8MB)

// pack two fp32 -> fp16x2 (lo, hi) as uint32
__device__ __forceinline__ uint32_t pack_h2(float lo, float hi) {
    uint32_t r;
    asm("cvt.rn.f16x2.f32 %0, %1, %2;" : "=r"(r) : "f"(hi), "f"(lo));
    return r;
}

// ---- fused routing ----
__global__ __launch_bounds__(1024) void k_route(const int* __restrict__ gate) {
    __shared__ int sc[NE];
    __shared__ int sfill[NE];
    const int tid = threadIdx.x;
    if (tid < NE) sc[tid] = 0;
    __syncthreads();
    for (int t = tid; t < NTOK; t += 1024) atomicAdd(&sc[gate[t]], 1);
    __syncthreads();
    if (tid == 0) {
        int s = 0, ts = 0;
        for (int e = 0; e < NE; e++) {
            g_off[e] = s; sfill[e] = s; g_tile[e] = ts;
            int c = sc[e];
            s += c; ts += (c + BM - 1) / BM;
        }
        g_off[NE] = s; g_tile[NE] = ts;
    }
    __syncthreads();
    for (int t = tid; t < NTOK; t += 1024) {
        int p = atomicAdd(&sfill[gate[t]], 1);
        g_sorted[p] = t;
    }
}

// ---- x -> fp16 once ----
__global__ void k_cvtx(const float* __restrict__ x) {
    int i = (blockIdx.x * 256 + threadIdx.x) * 8;
    float4 v0 = *(const float4*)(x + i);
    float4 v1 = *(const float4*)(x + i + 4);
    uint4 o;
    o.x = pack_h2(v0.x, v0.y);
    o.y = pack_h2(v0.z, v0.w);
    o.z = pack_h2(v1.x, v1.y);
    o.w = pack_h2(v1.z, v1.w);
    *(uint4*)(g_xh + i) = o;
}

// ---- helpers ----
__device__ __forceinline__ uint32_t smem_u32(const void* p) {
    uint32_t a;
    asm("{ .reg .u64 t; cvta.to.shared.u64 t, %1; cvt.u32.u64 %0, t; }" : "=r"(a) : "l"(p));
    return a;
}
__device__ __forceinline__ void cp16(uint32_t dst, const void* src, uint32_t srcsz) {
    asm volatile("cp.async.ca.shared.global [%0], [%1], 16, %2;"
                 :: "r"(dst), "l"(src), "r"(srcsz) : "memory");
}
#define CP_COMMIT() asm volatile("cp.async.commit_group;" ::: "memory")
#define CP_WAIT(n)  asm volatile("cp.async.wait_group %0;" :: "n"(n) : "memory")

__device__ __forceinline__ void mma_f16(float c[4], const uint32_t a[4], const uint32_t b[2]) {
    asm volatile(
        "mma.sync.aligned.m16n8k16.row.col.f32.f16.f16.f32 "
        "{%0,%1,%2,%3}, {%4,%5,%6,%7}, {%8,%9}, {%0,%1,%2,%3};"
        : "+f"(c[0]), "+f"(c[1]), "+f"(c[2]), "+f"(c[3])
        : "r"(a[0]), "r"(a[1]), "r"(a[2]), "r"(a[3]), "r"(b[0]), "r"(b[1]));
}
__device__ __forceinline__ void ldsm_x4(uint32_t r[4], uint32_t addr) {
    asm volatile("ldmatrix.sync.aligned.m8n8.x4.shared.b16 {%0,%1,%2,%3}, [%4];"
                 : "=r"(r[0]), "=r"(r[1]), "=r"(r[2]), "=r"(r[3]) : "r"(addr));
}

// SMEM halves: A0 @0, A1 @5120, B0 @10240, B1 @15360 (each 128*40=5120 halves)
#define B_OFF0 10240
#define SM_HALVES  20480
#define SMEM_BYTES (SM_HALVES * 2 + 512)

// ---- grouped GEMM: out[tok,n] = x[tok,:] . W[e,n,:] (fp16 mma, fp32 acc) ----
__global__ __launch_bounds__(256, 2) void k_gemm(
    const float* __restrict__ w,
    float* __restrict__ out)
{
    const int mt = blockIdx.x;
    if (mt >= g_tile[NE]) return;
    const int n0 = blockIdx.y * BN;

    extern __shared__ __half smh[];
    int* rowTok = (int*)(smh + SM_HALVES);

    const int tid = threadIdx.x;
    const int wid = tid >> 5;
    const int ln  = tid & 31;

    int e = 0;
#pragma unroll
    for (int i = 1; i < NE; i++) e += (mt >= g_tile[i]);
    const int seg_start = g_off[e];
    const int seg_cnt   = g_off[e + 1] - seg_start;
    const int m0        = (mt - g_tile[e]) * BM;

    if (tid < BM) {
        int idx = m0 + tid;
        rowTok[tid] = (idx < seg_cnt) ? g_sorted[seg_start + idx] : -1;
    }
    __syncthreads();

    const uint32_t sbase = smem_u32(smh);

    // ---- A loader: thread -> row tid>>1, two 16B units (tid&1)*2+{0,1} ----
    const int arowL = tid >> 1;
    const int aunit = (tid & 1) * 2;
    const int atok  = rowTok[arowL];
    const __half* axsrc = g_xh + (size_t)((atok < 0) ? 0 : atok) * INF + aunit * 8;
    const uint32_t aDstBase = sbase + (arowL * LDAH + aunit * 8) * 2;
    const uint32_t aZf = (atok < 0) ? 0u : 16u;

    // ---- W loader: thread -> row tid>>1, 16-float half (tid&1) ----
    const int wrowL = tid >> 1;
    const int whalf = tid & 1;
    const float* wsrc = w + (size_t)e * OUTF * INF + (size_t)(n0 + wrowL) * INF + whalf * 16;
    const uint32_t bDstBase = sbase + (B_OFF0 + wrowL * LDAH + whalf * 16) * 2;

    // ---- compute setup: warp (wm,wn) owns 64m x 32n ----
    const int wm = wid >> 2;
    const int wn = wid & 3;
    // A ldmatrix x4: lanes 0-15 -> m rows 0-15, lanes 16-31 same rows, +16B col
    const uint32_t aLdBase = sbase +
        ((wm * 64 + (ln & 15)) * LDAH + (ln >> 4) * 8) * 2;
    // B ldmatrix x4 (two 8-n tiles): lanes0-7 n0-7 k0; 8-15 n0-7 k8; 16-23 n8-15 k0; 24-31 n8-15 k8
    const uint32_t bLdBase = sbase +
        (B_OFF0 + (wn * 32 + (ln & 7) + ((ln >> 4) << 3)) * LDAH + (((ln >> 3) & 1) * 8)) * 2;

    float c[4][4][4];
#pragma unroll
    for (int i = 0; i < 4; i++)
#pragma unroll
        for (int j = 0; j < 4; j++) {
            c[i][j][0] = 0.f; c[i][j][1] = 0.f; c[i][j][2] = 0.f; c[i][j][3] = 0.f;
        }

    // ---- prologue: W chunk0 -> regs, x chunk0 -> smem A0 ----
    uint4 wv[4];
#pragma unroll
    for (int q = 0; q < 4; q++) wv[q] = *(const uint4*)(wsrc + q * 4);
    cp16(aDstBase,      axsrc,     aZf);
    cp16(aDstBase + 16, axsrc + 8, aZf);
    CP_COMMIT();

    for (int it = 0; it < NKI; it++) {
        const int buf = it & 1;
        const uint32_t bufB = (uint32_t)(buf * 5120 * 2);

        // convert W chunk it -> smem B[buf]
        {
            uint4 s0, s1;
            const float* f = (const float*)wv;
            s0.x = pack_h2(f[0],  f[1]);
            s0.y = pack_h2(f[2],  f[3]);
            s0.z = pack_h2(f[4],  f[5]);
            s0.w = pack_h2(f[6],  f[7]);
            s1.x = pack_h2(f[8],  f[9]);
            s1.y = pack_h2(f[10], f[11]);
            s1.z = pack_h2(f[12], f[13]);
            s1.w = pack_h2(f[14], f[15]);
            *(uint4*)((char*)smh + (bDstBase - sbase) + bufB)      = s0;
            *(uint4*)((char*)smh + (bDstBase - sbase) + bufB + 16) = s1;
        }

        if (it + 1 < NKI) {
            const int koff = (it + 1) * BK;
            // W chunk it+1 -> regs (latency hidden under MMA below)
#pragma unroll
            for (int q = 0; q < 4; q++) wv[q] = *(const uint4*)(wsrc + koff + q * 4);
            // x chunk it+1 -> smem A[buf^1]
            const uint32_t nbo = (uint32_t)(((it + 1) & 1) * 5120 * 2);
            cp16(aDstBase + nbo,      axsrc + koff,     aZf);
            cp16(aDstBase + nbo + 16, axsrc + koff + 8, aZf);
            CP_COMMIT();
            CP_WAIT(1);
        } else {
            CP_WAIT(0);
        }
        __syncthreads();

        const uint32_t aB = aLdBase + (uint32_t)(buf * 5120 * 2);
        const uint32_t bB = bLdBase + bufB;

#pragma unroll
        for (int ks = 0; ks < 2; ks++) {          // two k16 steps per chunk
            uint32_t a[4][4], b[2][4];
#pragma unroll
            for (int mtl = 0; mtl < 4; mtl++)
                ldsm_x4(a[mtl], aB + (mtl * 16 * LDAH + ks * 16) * 2);
#pragma unroll
            for (int np = 0; np < 2; np++)        // each covers two 8-n tiles
                ldsm_x4(b[np], bB + (np * 16 * LDAH + ks * 16) * 2);
#pragma unroll
            for (int mtl = 0; mtl < 4; mtl++)
#pragma unroll
                for (int nt = 0; nt < 4; nt++) {
                    const uint32_t bb[2] = { b[nt >> 1][(nt & 1) * 2],
                                             b[nt >> 1][(nt & 1) * 2 + 1] };
                    mma_f16(c[mtl][nt], a[mtl], bb);
                }
        }
        __syncthreads();
    }

    // ---- epilogue: scatter rows to original tokens ----
    const int colBase = n0 + wn * 32 + 2 * (ln & 3);
#pragma unroll
    for (int mtl = 0; mtl < 4; mtl++) {
        int r0 = wm * 64 + mtl * 16 + (ln >> 2);
        int tok0 = rowTok[r0];
        int tok1 = rowTok[r0 + 8];
        if (tok0 >= 0) {
            float* po = out + (size_t)tok0 * OUTF + colBase;
#pragma unroll
            for (int nt = 0; nt < 4; nt++)
                *(float2*)(po + nt * 8) = make_float2(c[mtl][nt][0], c[mtl][nt][1]);
        }
        if (tok1 >= 0) {
            float* po = out + (size_t)tok1 * OUTF + colBase;
#pragma unroll
            for (int nt = 0; nt < 4; nt++)
                *(float2*)(po + nt * 8) = make_float2(c[mtl][nt][2], c[mtl][nt][3]);
        }
    }
}

extern "C" void kernel_launch(void* const* d_in, const int* in_sizes, int n_in,
                              void* d_out, int out_size)
{
    const float* x    = (const float*)d_in[0];
    const int*   gate = (const int*)d_in[1];
    const float* w    = (const float*)d_in[2];
    float*       out  = (float*)d_out;

    cudaFuncSetAttribute(k_gemm, cudaFuncAttributeMaxDynamicSharedMemorySize, SMEM_BYTES);

    k_cvtx<<<NTOK * INF / 2048, 256>>>(x);
    k_route<<<1, 1024>>>(gate);

    dim3 grid(MAXMT, OUTF / BN);   // 48 x 16
    k_gemm<<<grid, 256, SMEM_BYTES>>>(w, out);
}

// round 7
// speedup vs baseline: 1.1185x; 1.1185x over previous
#include <cuda_runtime.h>
#include <cstdint>

#define NE    16
#define NTOK  4096
#define INF   1024
#define OUTF  2048
#define BM    128
#define BN    128
#define BK    32
#define NKI   (INF / BK)          // 32 k-chunks
#define MAXMT (NTOK / BM + NE)    // 48 worst-case m-tiles
#define LDA   36                  // smem row stride in floats (32 + 4 pad)

// ---- device scratch ----
__device__ int g_off[NE + 1];
__device__ int g_sorted[NTOK];
__device__ int g_tile[NE + 1];

// ---- fused routing: hist + scan + scatter in one block ----
__global__ __launch_bounds__(1024) void k_route(const int* __restrict__ gate) {
    __shared__ int sc[NE];
    __shared__ int sfill[NE];
    const int tid = threadIdx.x;
    if (tid < NE) sc[tid] = 0;
    __syncthreads();
    for (int t = tid; t < NTOK; t += 1024) atomicAdd(&sc[gate[t]], 1);
    __syncthreads();
    if (tid == 0) {
        int s = 0, ts = 0;
        for (int e = 0; e < NE; e++) {
            g_off[e] = s; sfill[e] = s; g_tile[e] = ts;
            int c = sc[e];
            s += c; ts += (c + BM - 1) / BM;
        }
        g_off[NE] = s; g_tile[NE] = ts;
    }
    __syncthreads();
    for (int t = tid; t < NTOK; t += 1024) {
        int p = atomicAdd(&sfill[gate[t]], 1);
        g_sorted[p] = t;
    }
}

// ---- helpers ----
__device__ __forceinline__ uint32_t smem_u32(const void* p) {
    uint32_t a;
    asm("{ .reg .u64 t; cvta.to.shared.u64 t, %1; cvt.u32.u64 %0, t; }" : "=r"(a) : "l"(p));
    return a;
}
__device__ __forceinline__ void cp16(uint32_t dst, const void* src, uint32_t srcsz) {
    asm volatile("cp.async.ca.shared.global [%0], [%1], 16, %2;"
                 :: "r"(dst), "l"(src), "r"(srcsz) : "memory");
}
#define CP_COMMIT() asm volatile("cp.async.commit_group;" ::: "memory")
#define CP_WAIT(n)  asm volatile("cp.async.wait_group %0;" :: "n"(n) : "memory")

__device__ __forceinline__ void mma_tf32(float c[4], const uint32_t a[4], const uint32_t b[2]) {
    asm volatile(
        "mma.sync.aligned.m16n8k8.row.col.f32.tf32.tf32.f32 "
        "{%0,%1,%2,%3}, {%4,%5,%6,%7}, {%8,%9}, {%0,%1,%2,%3};"
        : "+f"(c[0]), "+f"(c[1]), "+f"(c[2]), "+f"(c[3])
        : "r"(a[0]), "r"(a[1]), "r"(a[2]), "r"(a[3]), "r"(b[0]), "r"(b[1]));
}
__device__ __forceinline__ void ldsm_x4(uint32_t r[4], uint32_t addr) {
    asm volatile("ldmatrix.sync.aligned.m8n8.x4.shared.b16 {%0,%1,%2,%3}, [%4];"
                 : "=r"(r[0]), "=r"(r[1]), "=r"(r[2]), "=r"(r[3]) : "r"(addr));
}
__device__ __forceinline__ void ldsm_x2(uint32_t r[2], uint32_t addr) {
    asm volatile("ldmatrix.sync.aligned.m8n8.x2.shared.b16 {%0,%1}, [%2];"
                 : "=r"(r[0]), "=r"(r[1]) : "r"(addr));
}

// SMEM (floats): A at buf*9216, B at 4608 + buf*9216; rowTok after
#define SM_FLOATS  18432
#define SMEM_BYTES (SM_FLOATS * 4 + 512)
#define BUF_BYTES  (9216 * 4)

// ---- grouped GEMM: out[tok, n] = x[tok,:] . W[e, n, :] (tf32 mma, fp32 acc) ----
__global__ __launch_bounds__(256, 2) void k_gemm(
    const float* __restrict__ x,
    const float* __restrict__ w,
    float* __restrict__ out)
{
    const int mt = blockIdx.x;
    if (mt >= g_tile[NE]) return;
    const int n0 = blockIdx.y * BN;

    extern __shared__ float smf[];
    int* rowTok = (int*)(smf + SM_FLOATS);

    const int tid = threadIdx.x;
    const int wid = tid >> 5;
    const int ln  = tid & 31;

    int e = 0;
#pragma unroll
    for (int i = 1; i < NE; i++) e += (mt >= g_tile[i]);
    const int seg_start = g_off[e];
    const int seg_cnt   = g_off[e + 1] - seg_start;
    const int m0        = (mt - g_tile[e]) * BM;

    if (tid < BM) {
        int idx = m0 + tid;
        rowTok[tid] = (idx < seg_cnt) ? g_sorted[seg_start + idx] : -1;
    }
    __syncthreads();

    // ---- loader: thread -> rows (tid>>3)+32i, 16B unit (tid&7) ----
    const int lr = tid >> 3;
    const int lq = tid & 7;
    const float* wbase = w + (size_t)e * OUTF * INF;
    int ltok[4];
    const float* asrc[4];
    const float* bsrc[4];
#pragma unroll
    for (int i = 0; i < 4; i++) {
        int r = lr + 32 * i;
        ltok[i] = rowTok[r];
        asrc[i] = x + (size_t)((ltok[i] < 0) ? 0 : ltok[i]) * INF + lq * 4;
        bsrc[i] = wbase + (size_t)(n0 + r) * INF + lq * 4;
    }
    const uint32_t sbase = smem_u32(smf);
    uint32_t adst[4], bdst[4];
#pragma unroll
    for (int i = 0; i < 4; i++) {
        adst[i] = sbase + ((lr + 32 * i) * LDA + lq * 4) * 4;
        bdst[i] = sbase + (4608 + (lr + 32 * i) * LDA + lq * 4) * 4;
    }

    // ---- compute setup: warp (wm, wn) owns 64m x 32n ----
    const int wm = wid >> 2;
    const int wn = wid & 3;
    // A ldmatrix x4: matrices (r,k),(r+8,k),(r,k+4),(r+8,k+4)
    const int amat = ln >> 3;          // 0..3
    const int arow = wm * 64 + ((amat & 1) << 3) + (ln & 7);
    const uint32_t aOff0 = (uint32_t)((arow * LDA + (amat >> 1) * 4) * 4);
    // B x2: matrices (k0..3), (k4..7); lanes 0..15 supply addrs
    const int bmat = (ln >> 3) & 1;
    const int brow = wn * 32 + (ln & 7);
    const uint32_t bOff0 = (uint32_t)(((4608 + brow * LDA) + bmat * 4) * 4);

    float c[4][4][4];
#pragma unroll
    for (int i = 0; i < 4; i++)
#pragma unroll
        for (int j = 0; j < 4; j++) {
            c[i][j][0] = 0.f; c[i][j][1] = 0.f; c[i][j][2] = 0.f; c[i][j][3] = 0.f;
        }

    // prologue: chunk 0 -> buffer 0
#pragma unroll
    for (int i = 0; i < 4; i++) {
        cp16(adst[i], asrc[i], ltok[i] < 0 ? 0u : 16u);
        cp16(bdst[i], bsrc[i], 16u);
    }
    CP_COMMIT();

    for (int it = 0; it < NKI; it++) {
        const int cbuf = it & 1;
        if (it + 1 < NKI) {
            const uint32_t nbo = (uint32_t)(((it + 1) & 1) * BUF_BYTES);
            const int koff = (it + 1) * BK;
#pragma unroll
            for (int i = 0; i < 4; i++) {
                cp16(adst[i] + nbo, asrc[i] + koff, ltok[i] < 0 ? 0u : 16u);
                cp16(bdst[i] + nbo, bsrc[i] + koff, 16u);
            }
            CP_COMMIT();
            CP_WAIT(1);
        } else {
            CP_WAIT(0);
        }
        __syncthreads();

        const uint32_t aB = sbase + cbuf * BUF_BYTES + aOff0;
        const uint32_t bB = sbase + cbuf * BUF_BYTES + bOff0;

#pragma unroll
        for (int ks = 0; ks < 4; ks++) {
            uint32_t a[4][4], b[4][2];
#pragma unroll
            for (int mtl = 0; mtl < 4; mtl++)
                ldsm_x4(a[mtl], aB + (mtl * 16 * LDA + ks * 8) * 4);
#pragma unroll
            for (int nt = 0; nt < 4; nt++)
                ldsm_x2(b[nt], bB + (nt * 8 * LDA + ks * 8) * 4);
#pragma unroll
            for (int mtl = 0; mtl < 4; mtl++)
#pragma unroll
                for (int nt = 0; nt < 4; nt++)
                    mma_tf32(c[mtl][nt], a[mtl], b[nt]);
        }
        __syncthreads();
    }

    // ---- epilogue: scatter rows to original tokens ----
    const int colBase = n0 + wn * 32 + 2 * (ln & 3);
#pragma unroll
    for (int mtl = 0; mtl < 4; mtl++) {
        int r0 = wm * 64 + mtl * 16 + (ln >> 2);
        int tok0 = rowTok[r0];
        int tok1 = rowTok[r0 + 8];
        if (tok0 >= 0) {
            float* po = out + (size_t)tok0 * OUTF + colBase;
#pragma unroll
            for (int nt = 0; nt < 4; nt++)
                *(float2*)(po + nt * 8) = make_float2(c[mtl][nt][0], c[mtl][nt][1]);
        }
        if (tok1 >= 0) {
            float* po = out + (size_t)tok1 * OUTF + colBase;
#pragma unroll
            for (int nt = 0; nt < 4; nt++)
                *(float2*)(po + nt * 8) = make_float2(c[mtl][nt][2], c[mtl][nt][3]);
        }
    }
}

extern "C" void kernel_launch(void* const* d_in, const int* in_sizes, int n_in,
                              void* d_out, int out_size)
{
    const float* x    = (const float*)d_in[0];
    const int*   gate = (const int*)d_in[1];
    const float* w    = (const float*)d_in[2];
    float*       out  = (float*)d_out;

    cudaFuncSetAttribute(k_gemm, cudaFuncAttributeMaxDynamicSharedMemorySize, SMEM_BYTES);

    k_route<<<1, 1024>>>(gate);

    dim3 grid(MAXMT, OUTF / BN);   // 48 x 16
    k_gemm<<<grid, 256, SMEM_BYTES>>>(x, w, out);
}